// round 12
// baseline (speedup 1.0000x reference)
#include <cuda_runtime.h>
#include <cuda_bf16.h>
#include <cstdint>

#define NB_ROWS 8192
#define ND_IN   768
#define ND_HID  16384
#define K_TOP   32
#define NCAND   192
#define T0      2.45f          // nomination threshold (latent ~ N(0,1), v32 ~ 2.88)
#define FB_MIN  44             // fallback trigger: cnt < FB_MIN or cnt > NCAND
#define BAND    0.03f          // fp64-refine band below approx 32nd value

#define KDIM   ND_IN           // 768
#define TM     128
#define TN     128
#define BK     64              // bf16 per chunk (128 bytes per row)
#define NCHUNK (KDIM / BK)     // 12
#define NSTAGE 3
#define STAGE_BYTES 32768      // A 16KB + B 16KB
#define SMEM_REQ (NSTAGE * STAGE_BYTES)   // 96KB -> 2 CTAs/SM

// ---------------- device scratch (static, allocation-free) ----------------
__device__ __align__(256) __nv_bfloat16 g_Ab[(size_t)NB_ROWS * KDIM];   // 12.6 MB
__device__ __align__(256) __nv_bfloat16 g_Bb[(size_t)ND_HID * KDIM];    // 25 MB
__device__ float g_WdecT[(size_t)ND_HID * ND_IN];                       // 50 MB
__device__ int   g_tk_idx[NB_ROWS * K_TOP];
__device__ float g_tk_val[NB_ROWS * K_TOP];
__device__ int   g_cand_idx[NB_ROWS * NCAND];
__device__ float g_cand_val[NB_ROWS * NCAND];
__device__ int   g_cand_cnt[NB_ROWS];

// ---------------- PTX helpers (baseline compute_103 only!) ----------------
__device__ __forceinline__ uint32_t smem_u32(const void* p) {
    uint32_t a;
    asm("{ .reg .u64 t; cvta.to.shared.u64 t, %1; cvt.u32.u64 %0, t; }" : "=r"(a) : "l"(p));
    return a;
}

__device__ __forceinline__ void cp16(uint32_t dst, const void* src) {
    asm volatile("cp.async.cg.shared.global [%0], [%1], 16;" :: "r"(dst), "l"(src));
}
#define CP_COMMIT() asm volatile("cp.async.commit_group;" ::: "memory")
#define CP_WAIT2()  asm volatile("cp.async.wait_group 2;" ::: "memory")

__device__ __forceinline__ void ldsm4(uint32_t& r0, uint32_t& r1, uint32_t& r2, uint32_t& r3,
                                      uint32_t addr) {
    asm volatile("ldmatrix.sync.aligned.m8n8.x4.shared.b16 {%0,%1,%2,%3}, [%4];"
                 : "=r"(r0), "=r"(r1), "=r"(r2), "=r"(r3) : "r"(addr));
}

__device__ __forceinline__ void mma16816(float* c, uint32_t a0, uint32_t a1, uint32_t a2,
                                         uint32_t a3, uint32_t b0, uint32_t b1) {
    asm volatile(
        "mma.sync.aligned.m16n8k16.row.col.f32.bf16.bf16.f32 "
        "{%0,%1,%2,%3}, {%4,%5,%6,%7}, {%8,%9}, {%0,%1,%2,%3};"
        : "+f"(c[0]), "+f"(c[1]), "+f"(c[2]), "+f"(c[3])
        : "r"(a0), "r"(a1), "r"(a2), "r"(a3), "r"(b0), "r"(b1));
}

// =====================================================================
// Prep: fp32 -> bf16 conversion + zero kernels
// =====================================================================
__global__ void conv_x_kernel(const float* __restrict__ X) {
    int i = (blockIdx.x * 256 + threadIdx.x) * 4;
    float4 v = *(const float4*)(X + i);
    __nv_bfloat16 b[4] = { __float2bfloat16_rn(v.x), __float2bfloat16_rn(v.y),
                           __float2bfloat16_rn(v.z), __float2bfloat16_rn(v.w) };
    *(uint2*)(g_Ab + i) = *(uint2*)b;
}
__global__ void conv_w_kernel(const float* __restrict__ W) {
    int i = (blockIdx.x * 256 + threadIdx.x) * 4;
    float4 v = *(const float4*)(W + i);
    __nv_bfloat16 b[4] = { __float2bfloat16_rn(v.x), __float2bfloat16_rn(v.y),
                           __float2bfloat16_rn(v.z), __float2bfloat16_rn(v.w) };
    *(uint2*)(g_Bb + i) = *(uint2*)b;
}
__global__ void zero_cnt_kernel() {
    g_cand_cnt[blockIdx.x * 256 + threadIdx.x] = 0;
}
__global__ void zero_latent_kernel(float* __restrict__ L) {
    size_t i = ((size_t)blockIdx.x * 256 + threadIdx.x) * 4;
    *(float4*)(L + i) = make_float4(0.f, 0.f, 0.f, 0.f);
}

// =====================================================================
// Warp-MMA GEMM (bf16) with fused threshold nomination. No dense store.
// CTA 128x128, 8 warps (2Mx4N), warp tile 64x32, 3-stage cp.async,
// 2 CTAs/SM. Values >= T0 appended to per-row candidate lists.
// =====================================================================
__global__ void __launch_bounds__(256, 2) wm_gemm_kernel()
{
    extern __shared__ __align__(128) char smem_raw[];
    const uint32_t smem = smem_u32(smem_raw);

    const int tid  = threadIdx.x;
    const int wid  = tid >> 5;
    const int lane = tid & 31;
    const int wm   = wid & 1;        // 2 warp-rows (M)
    const int wn   = wid >> 1;       // 4 warp-cols (N)
    const int m0 = blockIdx.x * TM;  // M fastest
    const int n0 = blockIdx.y * TN;

    auto load_chunk = [&](int t, int s) {
        const char* Ab = (const char*)g_Ab;
        const char* Bb = (const char*)g_Bb;
        const size_t kb = (size_t)t * (BK * 2);
        const uint32_t aS = smem + s * STAGE_BYTES;
        const uint32_t bS = aS + 16384;
        #pragma unroll
        for (int i = 0; i < 4; ++i) {                 // A: 1024 x 16B
            int gi = tid + (i << 8);
            int r = gi >> 3, g = gi & 7;
            uint32_t col = g * 16;
            uint32_t off = r * 128 + (col ^ ((r & 7) << 4));
            cp16(aS + off, Ab + (size_t)(m0 + r) * (KDIM * 2) + kb + col);
        }
        #pragma unroll
        for (int i = 0; i < 4; ++i) {                 // B: 1024 x 16B
            int gi = tid + (i << 8);
            int r = gi >> 3, g = gi & 7;
            uint32_t col = g * 16;
            uint32_t off = r * 128 + (col ^ ((r & 7) << 4));
            cp16(bS + off, Bb + (size_t)(n0 + r) * (KDIM * 2) + kb + col);
        }
        CP_COMMIT();
    };

    const int lr = lane & 15;
    const uint32_t lc = (lane >> 4) * 16;
    const uint32_t xr = (uint32_t)(lr & 7) << 4;
    uint32_t rbA[4], rbB[2];
    #pragma unroll
    for (int mt = 0; mt < 4; ++mt) rbA[mt] = (uint32_t)(wm * 64 + mt * 16 + lr) * 128;
    #pragma unroll
    for (int p = 0; p < 2; ++p)    rbB[p]  = (uint32_t)(wn * 32 + p * 16 + lr) * 128;

    float acc[4][4][4];
    #pragma unroll
    for (int a = 0; a < 4; ++a)
        #pragma unroll
        for (int b = 0; b < 4; ++b)
            #pragma unroll
            for (int c = 0; c < 4; ++c) acc[a][b][c] = 0.0f;

    load_chunk(0, 0);
    load_chunk(1, 1);

    for (int t = 0; t < NCHUNK; ++t) {
        if (t + 2 < NCHUNK) load_chunk(t + 2, (t + 2) % NSTAGE);
        else                CP_COMMIT();
        CP_WAIT2();
        __syncthreads();

        const uint32_t aS = smem + (t % NSTAGE) * STAGE_BYTES;
        const uint32_t bS = aS + 16384;
        #pragma unroll
        for (int ks = 0; ks < 4; ++ks) {
            const uint32_t colb = (ks * 32 + lc) ^ xr;
            uint32_t af[4][4], bf[2][4];
            #pragma unroll
            for (int mt = 0; mt < 4; ++mt)
                ldsm4(af[mt][0], af[mt][1], af[mt][2], af[mt][3], aS + rbA[mt] + colb);
            #pragma unroll
            for (int p = 0; p < 2; ++p)
                ldsm4(bf[p][0], bf[p][1], bf[p][2], bf[p][3], bS + rbB[p] + colb);
            #pragma unroll
            for (int mt = 0; mt < 4; ++mt)
                #pragma unroll
                for (int j = 0; j < 4; ++j) {
                    const int p = j >> 1, h = j & 1;
                    mma16816(acc[mt][j], af[mt][0], af[mt][1], af[mt][2], af[mt][3],
                             bf[p][h], bf[p][h + 2]);
                }
        }
        __syncthreads();
    }

    // ---- fused epilogue: threshold nomination, no dense store ----
    const int gid = lane >> 2;
    const int tig = lane & 3;
    #pragma unroll
    for (int mt = 0; mt < 4; ++mt) {
        const int r0 = m0 + wm * 64 + mt * 16 + gid;
        #pragma unroll
        for (int j = 0; j < 4; ++j) {
            const int col = n0 + wn * 32 + j * 8 + tig * 2;
            const int   rr[4]  = { r0, r0, r0 + 8, r0 + 8 };
            const int   cc[4]  = { col, col + 1, col, col + 1 };
            #pragma unroll
            for (int q = 0; q < 4; ++q) {
                float v = acc[mt][j][q];
                if (v >= T0) {
                    int rI = rr[q];
                    int s = atomicAdd(&g_cand_cnt[rI], 1);
                    if (s < NCAND) {
                        g_cand_idx[rI * NCAND + s] = cc[q];
                        g_cand_val[rI * NCAND + s] = v;
                    }
                }
            }
        }
    }
}

// =====================================================================
// Fallback: rows with suspicious candidate counts get an exact fp32
// full-row recompute + bisection-based candidate rebuild. ~never runs.
// =====================================================================
__device__ __forceinline__ int fb_count_ge(const unsigned int* u, unsigned int X,
                                           int tid, int* s_red)
{
    int c = 0;
    const uint4* p = (const uint4*)u;
    #pragma unroll
    for (int i = 0; i < ND_HID / 4 / 256; ++i) {
        uint4 v = p[tid + (i << 8)];
        c += (v.x >= X) + (v.y >= X) + (v.z >= X) + (v.w >= X);
    }
    #pragma unroll
    for (int o = 16; o; o >>= 1) c += __shfl_xor_sync(0xffffffffu, c, o);
    if ((tid & 31) == 0) s_red[tid >> 5] = c;
    __syncthreads();
    int total = 0;
    #pragma unroll
    for (int w = 0; w < 8; ++w) total += s_red[w];
    __syncthreads();
    return total;
}

__global__ void __launch_bounds__(256) fallback_kernel(
    const float* __restrict__ X, const float* __restrict__ W)
{
    const int row = blockIdx.x;
    const int cnt0 = g_cand_cnt[row];
    if (cnt0 >= FB_MIN && cnt0 <= NCAND) return;

    extern __shared__ unsigned int u[];            // 16384 bits + 768 x floats
    float* xs = (float*)(u + ND_HID);
    __shared__ int s_red[8];
    __shared__ int s_slot;

    const int tid = threadIdx.x;
    for (int k = tid; k < ND_IN; k += 256) xs[k] = X[(size_t)row * ND_IN + k];
    if (tid == 0) s_slot = 0;
    __syncthreads();

    for (int j = tid; j < ND_HID; j += 256) {
        const float* w = W + (size_t)j * ND_IN;
        float s = 0.f;
        #pragma unroll 4
        for (int k = 0; k < ND_IN; k += 4) {
            float4 wv = *(const float4*)(w + k);
            s += xs[k] * wv.x + xs[k+1] * wv.y + xs[k+2] * wv.z + xs[k+3] * wv.w;
        }
        u[j] = __float_as_uint(fmaxf(s, 0.f));
    }
    __syncthreads();

    unsigned int P = 0;
    bool exact = false;
    for (int bit = 30; bit >= 0 && !exact; --bit) {
        unsigned int cand = P | (1u << bit);
        int c = fb_count_ge(u, cand, tid, s_red);
        if (c >= K_TOP) { P = cand; if (c == K_TOP) exact = true; }
    }
    const float Tf = __uint_as_float(P) - BAND;

    int* ci = g_cand_idx + row * NCAND;
    float* cv = g_cand_val + row * NCAND;
    for (int i = tid; i < ND_HID; i += 256) {
        float f = __uint_as_float(u[i]);
        if (f >= Tf) {
            int s = atomicAdd(&s_slot, 1);
            if (s < NCAND) { ci[s] = i; cv[s] = f; }
        }
    }
    __syncthreads();
    if (tid == 0) g_cand_cnt[row] = (s_slot < NCAND) ? s_slot : NCAND;
}

// =====================================================================
// Refine + select: approx-rank candidates, fp64-refine the ~35 within
// BAND of the approx 32nd value, final rank (value desc, index asc =
// jax), scatter top-32 into latent + (idx,val) list.
// =====================================================================
__global__ void __launch_bounds__(256) refsel_kernel(
    const float* __restrict__ X, const float* __restrict__ W, float* __restrict__ latent)
{
    __shared__ float sv[NCAND];
    __shared__ int   si[NCAND];
    __shared__ float rv[NCAND];
    __shared__ short ridx[NCAND];
    __shared__ float xs[ND_IN];
    __shared__ int   s_m;
    __shared__ float s_v32;

    const int row = blockIdx.x;
    const int t = threadIdx.x;
    const int wid = t >> 5, lane = t & 31;
    int cnt = g_cand_cnt[row];
    if (cnt > NCAND) cnt = NCAND;

    if (t < NCAND) {
        sv[t] = (t < cnt) ? g_cand_val[row * NCAND + t] : -1e30f;
        si[t] = (t < cnt) ? g_cand_idx[row * NCAND + t] : 0x7fffffff;
        rv[t] = -1e30f;
    }
    for (int k = t; k < ND_IN; k += 256) xs[k] = X[(size_t)row * ND_IN + k];
    if (t == 0) s_m = 0;
    if (t < K_TOP) { g_tk_idx[row * K_TOP + t] = 0; g_tk_val[row * K_TOP + t] = 0.0f; }
    __syncthreads();

    // approx rank -> 32nd approx value
    if (t < cnt) {
        const float v = sv[t];
        const int  ix = si[t];
        int rank = 0;
        #pragma unroll 8
        for (int j = 0; j < NCAND; ++j)
            rank += (sv[j] > v) || (sv[j] == v && si[j] < ix);
        if (rank == K_TOP - 1) s_v32 = v;
    }
    __syncthreads();
    const float band = s_v32 - BAND;

    // compact refine set
    if (t < cnt && sv[t] >= band) {
        int p = atomicAdd(&s_m, 1);
        ridx[p] = (short)t;
    }
    __syncthreads();
    const int m = s_m;

    // fp64 dots, one warp per refined candidate
    for (int r = wid; r < m; r += 8) {
        const int c = ridx[r];
        const float* w = W + (size_t)si[c] * ND_IN;
        double s = 0.0;
        #pragma unroll 4
        for (int k = lane; k < ND_IN; k += 32) s = fma((double)xs[k], (double)w[k], s);
        #pragma unroll
        for (int o = 16; o; o >>= 1) s += __shfl_xor_sync(0xffffffffu, s, o);
        if (lane == 0) rv[c] = (float)(s > 0.0 ? s : 0.0);
    }
    __syncthreads();

    // final rank among refined (unrefined are -1e30) + scatter
    if (t < cnt && rv[t] > -1e29f) {
        const float v = rv[t];
        const int  ix = si[t];
        int rank = 0;
        #pragma unroll 8
        for (int j = 0; j < NCAND; ++j)
            rank += (rv[j] > v) || (rv[j] == v && si[j] < ix);
        if (rank < K_TOP) {
            latent[(size_t)row * ND_HID + ix] = v;
            g_tk_idx[row * K_TOP + rank] = ix;
            g_tk_val[row * K_TOP + rank] = v;
        }
    }
}

// =====================================================================
// transpose W_dec -> g_WdecT
// =====================================================================
__global__ void transpose_kernel(const float* __restrict__ W)
{
    __shared__ float t[32][33];
    const int tx = threadIdx.x, ty = threadIdx.y;
    const int h0 = blockIdx.x * 32;
    const int i0 = blockIdx.y * 32;
    #pragma unroll
    for (int j = ty; j < 32; j += 8)
        t[j][tx] = W[(size_t)(i0 + j) * ND_HID + h0 + tx];
    __syncthreads();
    #pragma unroll
    for (int j = ty; j < 32; j += 8)
        g_WdecT[(size_t)(h0 + j) * ND_IN + i0 + tx] = t[tx][j];
}

// =====================================================================
// sparse decoder
// =====================================================================
__global__ void __launch_bounds__(256) recon_kernel(float* __restrict__ recon)
{
    __shared__ int   si[K_TOP];
    __shared__ float sv[K_TOP];
    const int row = blockIdx.x;
    const int tid = threadIdx.x;
    if (tid < K_TOP) {
        si[tid] = g_tk_idx[row * K_TOP + tid];
        sv[tid] = g_tk_val[row * K_TOP + tid];
    }
    __syncthreads();
    float a0 = 0.f, a1 = 0.f, a2 = 0.f;
    #pragma unroll 4
    for (int j = 0; j < K_TOP; ++j) {
        const float* w = g_WdecT + (size_t)si[j] * ND_IN;
        float v = sv[j];
        a0 += v * w[tid];
        a1 += v * w[tid + 256];
        a2 += v * w[tid + 512];
    }
    float* r = recon + (size_t)row * ND_IN;
    r[tid] = a0; r[tid + 256] = a1; r[tid + 512] = a2;
}

// =====================================================================
extern "C" void kernel_launch(void* const* d_in, const int* in_sizes, int n_in,
                              void* d_out, int out_size)
{
    (void)in_sizes; (void)n_in; (void)out_size;
    const float* x     = (const float*)d_in[0];
    const float* W_enc = (const float*)d_in[1];
    const float* W_dec = (const float*)d_in[2];
    float* latent = (float*)d_out;
    float* recon  = (float*)d_out + (size_t)NB_ROWS * ND_HID;

    // 0) bf16 operand conversion + counter zeroing
    conv_x_kernel<<<NB_ROWS * ND_IN / 1024, 256>>>(x);
    conv_w_kernel<<<ND_HID * ND_IN / 1024, 256>>>(W_enc);
    zero_cnt_kernel<<<NB_ROWS / 256, 256>>>();

    // 1) bf16 warp-MMA GEMM with fused threshold nomination (no dense store)
    cudaFuncSetAttribute(wm_gemm_kernel, cudaFuncAttributeMaxDynamicSharedMemorySize, SMEM_REQ);
    wm_gemm_kernel<<<dim3(NB_ROWS / TM, ND_HID / TN), 256, SMEM_REQ>>>();

    // 2) zero the latent output region (only top-32 scattered later)
    zero_latent_kernel<<<NB_ROWS * ND_HID / 1024, 256>>>(latent);

    // 3) exact fallback for suspicious rows (early-exit otherwise)
    cudaFuncSetAttribute(fallback_kernel, cudaFuncAttributeMaxDynamicSharedMemorySize,
                         ND_HID * 4 + ND_IN * 4);
    fallback_kernel<<<NB_ROWS, 256, ND_HID * 4 + ND_IN * 4>>>(x, W_enc);

    // 4) fp64 refine + select + scatter
    refsel_kernel<<<NB_ROWS, 256>>>(x, W_enc, latent);

    // 5) transpose decoder weights
    transpose_kernel<<<dim3(ND_HID / 32, ND_IN / 32), dim3(32, 8)>>>(W_dec);

    // 6) sparse decoder
    recon_kernel<<<NB_ROWS, 256>>>(recon);
}

// round 14
// speedup vs baseline: 2.5089x; 2.5089x over previous
#include <cuda_runtime.h>
#include <cuda_bf16.h>
#include <cstdint>

#define NB_ROWS 8192
#define ND_IN   768
#define ND_HID  16384
#define K_TOP   32
#define NCAND   128
#define NBIN    512
#define BAND2   0.03f          // fp64-refine band below approx 32nd value

#define KDIM   ND_IN           // 768
#define TM     128
#define TN     128
#define BK     64              // bf16 per chunk (128 bytes per row)
#define NCHUNK (KDIM / BK)     // 12
#define NSTAGE 3
#define STAGE_BYTES 32768      // A 16KB + B 16KB
#define SMEM_REQ (NSTAGE * STAGE_BYTES)   // 96KB -> 2 CTAs/SM

// ---------------- device scratch (static, allocation-free) ----------------
__device__ __align__(256) __nv_bfloat16 g_Ab[(size_t)NB_ROWS * KDIM];   // 12.6 MB
__device__ __align__(256) __nv_bfloat16 g_Bb[(size_t)ND_HID * KDIM];    // 25 MB
__device__ float g_WdecT[(size_t)ND_HID * ND_IN];                       // 50 MB
__device__ int   g_tk_idx[NB_ROWS * K_TOP];
__device__ float g_tk_val[NB_ROWS * K_TOP];
__device__ int   g_cand_idx[NB_ROWS * NCAND];
__device__ float g_cand_val[NB_ROWS * NCAND];
__device__ int   g_cand_cnt[NB_ROWS];

// ---------------- PTX helpers (baseline compute_103 only!) ----------------
__device__ __forceinline__ uint32_t smem_u32(const void* p) {
    uint32_t a;
    asm("{ .reg .u64 t; cvta.to.shared.u64 t, %1; cvt.u32.u64 %0, t; }" : "=r"(a) : "l"(p));
    return a;
}

__device__ __forceinline__ void cp16(uint32_t dst, const void* src) {
    asm volatile("cp.async.cg.shared.global [%0], [%1], 16;" :: "r"(dst), "l"(src));
}
#define CP_COMMIT() asm volatile("cp.async.commit_group;" ::: "memory")
#define CP_WAIT2()  asm volatile("cp.async.wait_group 2;" ::: "memory")

__device__ __forceinline__ void ldsm4(uint32_t& r0, uint32_t& r1, uint32_t& r2, uint32_t& r3,
                                      uint32_t addr) {
    asm volatile("ldmatrix.sync.aligned.m8n8.x4.shared.b16 {%0,%1,%2,%3}, [%4];"
                 : "=r"(r0), "=r"(r1), "=r"(r2), "=r"(r3) : "r"(addr));
}

__device__ __forceinline__ void mma16816(float* c, uint32_t a0, uint32_t a1, uint32_t a2,
                                         uint32_t a3, uint32_t b0, uint32_t b1) {
    asm volatile(
        "mma.sync.aligned.m16n8k16.row.col.f32.bf16.bf16.f32 "
        "{%0,%1,%2,%3}, {%4,%5,%6,%7}, {%8,%9}, {%0,%1,%2,%3};"
        : "+f"(c[0]), "+f"(c[1]), "+f"(c[2]), "+f"(c[3])
        : "r"(a0), "r"(a1), "r"(a2), "r"(a3), "r"(b0), "r"(b1));
}

// =====================================================================
// Prep: fp32 -> bf16 conversion (coalesced)
// =====================================================================
__global__ void conv_x_kernel(const float* __restrict__ X) {
    int i = (blockIdx.x * 256 + threadIdx.x) * 4;
    float4 v = *(const float4*)(X + i);
    __nv_bfloat16 b[4] = { __float2bfloat16_rn(v.x), __float2bfloat16_rn(v.y),
                           __float2bfloat16_rn(v.z), __float2bfloat16_rn(v.w) };
    *(uint2*)(g_Ab + i) = *(uint2*)b;
}
__global__ void conv_w_kernel(const float* __restrict__ W) {
    int i = (blockIdx.x * 256 + threadIdx.x) * 4;
    float4 v = *(const float4*)(W + i);
    __nv_bfloat16 b[4] = { __float2bfloat16_rn(v.x), __float2bfloat16_rn(v.y),
                           __float2bfloat16_rn(v.z), __float2bfloat16_rn(v.w) };
    *(uint2*)(g_Bb + i) = *(uint2*)b;
}

// =====================================================================
// Warp-MMA GEMM (bf16): L[m,n] = relu( sum_k A[m,k]*B[n,k] )
// CTA 128x128, 8 warps (2Mx4N), warp tile 64x32, 3-stage cp.async,
// 2 CTAs/SM (measured 589us). Dense relu store.
// =====================================================================
__global__ void __launch_bounds__(256, 2) wm_gemm_kernel(float* __restrict__ L)
{
    extern __shared__ __align__(128) char smem_raw[];
    const uint32_t smem = smem_u32(smem_raw);

    const int tid  = threadIdx.x;
    const int wid  = tid >> 5;
    const int lane = tid & 31;
    const int wm   = wid & 1;        // 2 warp-rows (M)
    const int wn   = wid >> 1;       // 4 warp-cols (N)
    const int m0 = blockIdx.x * TM;  // M fastest
    const int n0 = blockIdx.y * TN;

    auto load_chunk = [&](int t, int s) {
        const char* Ab = (const char*)g_Ab;
        const char* Bb = (const char*)g_Bb;
        const size_t kb = (size_t)t * (BK * 2);
        const uint32_t aS = smem + s * STAGE_BYTES;
        const uint32_t bS = aS + 16384;
        #pragma unroll
        for (int i = 0; i < 4; ++i) {                 // A: 1024 x 16B
            int gi = tid + (i << 8);
            int r = gi >> 3, g = gi & 7;
            uint32_t col = g * 16;
            uint32_t off = r * 128 + (col ^ ((r & 7) << 4));
            cp16(aS + off, Ab + (size_t)(m0 + r) * (KDIM * 2) + kb + col);
        }
        #pragma unroll
        for (int i = 0; i < 4; ++i) {                 // B: 1024 x 16B
            int gi = tid + (i << 8);
            int r = gi >> 3, g = gi & 7;
            uint32_t col = g * 16;
            uint32_t off = r * 128 + (col ^ ((r & 7) << 4));
            cp16(bS + off, Bb + (size_t)(n0 + r) * (KDIM * 2) + kb + col);
        }
        CP_COMMIT();
    };

    const int lr = lane & 15;
    const uint32_t lc = (lane >> 4) * 16;
    const uint32_t xr = (uint32_t)(lr & 7) << 4;
    uint32_t rbA[4], rbB[2];
    #pragma unroll
    for (int mt = 0; mt < 4; ++mt) rbA[mt] = (uint32_t)(wm * 64 + mt * 16 + lr) * 128;
    #pragma unroll
    for (int p = 0; p < 2; ++p)    rbB[p]  = (uint32_t)(wn * 32 + p * 16 + lr) * 128;

    float acc[4][4][4];
    #pragma unroll
    for (int a = 0; a < 4; ++a)
        #pragma unroll
        for (int b = 0; b < 4; ++b)
            #pragma unroll
            for (int c = 0; c < 4; ++c) acc[a][b][c] = 0.0f;

    load_chunk(0, 0);
    load_chunk(1, 1);

    for (int t = 0; t < NCHUNK; ++t) {
        if (t + 2 < NCHUNK) load_chunk(t + 2, (t + 2) % NSTAGE);
        else                CP_COMMIT();
        CP_WAIT2();
        __syncthreads();

        const uint32_t aS = smem + (t % NSTAGE) * STAGE_BYTES;
        const uint32_t bS = aS + 16384;
        #pragma unroll
        for (int ks = 0; ks < 4; ++ks) {
            const uint32_t colb = (ks * 32 + lc) ^ xr;
            uint32_t af[4][4], bf[2][4];
            #pragma unroll
            for (int mt = 0; mt < 4; ++mt)
                ldsm4(af[mt][0], af[mt][1], af[mt][2], af[mt][3], aS + rbA[mt] + colb);
            #pragma unroll
            for (int p = 0; p < 2; ++p)
                ldsm4(bf[p][0], bf[p][1], bf[p][2], bf[p][3], bS + rbB[p] + colb);
            #pragma unroll
            for (int mt = 0; mt < 4; ++mt)
                #pragma unroll
                for (int j = 0; j < 4; ++j) {
                    const int p = j >> 1, h = j & 1;
                    mma16816(acc[mt][j], af[mt][0], af[mt][1], af[mt][2], af[mt][3],
                             bf[p][h], bf[p][h + 2]);
                }
        }
        __syncthreads();
    }

    // ---- epilogue: relu + float2 dense store ----
    const int gid = lane >> 2;
    const int tig = lane & 3;
    #pragma unroll
    for (int mt = 0; mt < 4; ++mt) {
        const int r0 = m0 + wm * 64 + mt * 16 + gid;
        #pragma unroll
        for (int j = 0; j < 4; ++j) {
            const int col = n0 + wn * 32 + j * 8 + tig * 2;
            float2 lo, hi;
            lo.x = fmaxf(acc[mt][j][0], 0.0f); lo.y = fmaxf(acc[mt][j][1], 0.0f);
            hi.x = fmaxf(acc[mt][j][2], 0.0f); hi.y = fmaxf(acc[mt][j][3], 0.0f);
            *(float2*)(L + (size_t)r0 * ND_HID + col)       = lo;
            *(float2*)(L + (size_t)(r0 + 8) * ND_HID + col) = hi;
        }
    }
}

// =====================================================================
// T1: candidate nomination, no smem row buffer (full occupancy).
// Pass 1: histogram (512 bins on float bits >= 1.0).
// Cutoff = edge(b*) - 0.06 (>= 26 sigma of bf16 GEMM error).
// Pass 2: re-read row (L2-hot), collect idx+val, zero-store row.
// =====================================================================
__global__ void __launch_bounds__(256) cand_kernel(float* __restrict__ latent)
{
    __shared__ int hist[NBIN];
    __shared__ int s_slot;
    __shared__ float s_Tf;

    const int row = blockIdx.x;
    const int tid = threadIdx.x;
    float* Lrow = latent + (size_t)row * ND_HID;

    #pragma unroll
    for (int b = tid; b < NBIN; b += 256) hist[b] = 0;
    if (tid == 0) s_slot = 0;
    __syncthreads();

    const uint4* g4 = (const uint4*)Lrow;
    #pragma unroll
    for (int i = 0; i < ND_HID / 4 / 256; ++i) {
        uint4 v = g4[tid + (i << 8)];
        unsigned int w[4] = { v.x, v.y, v.z, v.w };
        #pragma unroll
        for (int j = 0; j < 4; ++j)
            if (w[j] >= 0x3F800000u) {   // relu'd latent: all bits are non-negative floats
                unsigned int b = (w[j] - 0x3F800000u) >> 16;
                atomicAdd(&hist[b < NBIN ? b : NBIN - 1], 1);
            }
    }
    __syncthreads();

    if (tid == 0) {
        int cum = 0, bstar = -1;
        for (int b = NBIN - 1; b >= 0; --b) {
            cum += hist[b];
            if (cum >= K_TOP) { bstar = b; break; }
        }
        s_Tf = (bstar >= 0)
             ? __uint_as_float(0x3F800000u + ((unsigned)bstar << 16)) - 0.06f
             : 0.0f;   // statistically unreachable
    }
    __syncthreads();
    const float Tf = s_Tf;

    int*   ci = g_cand_idx + row * NCAND;
    float* cv = g_cand_val + row * NCAND;
    uint4* w4 = (uint4*)Lrow;
    const uint4 z = make_uint4(0, 0, 0, 0);
    #pragma unroll
    for (int i = 0; i < ND_HID / 4 / 256; ++i) {
        const int base = (tid + (i << 8)) * 4;
        uint4 v = g4[tid + (i << 8)];        // L2 hit (just read in pass 1)
        float f[4] = { __uint_as_float(v.x), __uint_as_float(v.y),
                       __uint_as_float(v.z), __uint_as_float(v.w) };
        #pragma unroll
        for (int j = 0; j < 4; ++j)
            if (f[j] >= Tf) {
                int s = atomicAdd(&s_slot, 1);
                if (s < NCAND) { ci[s] = base + j; cv[s] = f[j]; }
            }
        w4[tid + (i << 8)] = z;              // zero the row in place
    }
    __syncthreads();
    if (tid == 0) g_cand_cnt[row] = (s_slot < NCAND) ? s_slot : NCAND;
}

// =====================================================================
// T2: refine + select (validated in round 12 — bit-identical output to
// full-refine). Approx-rank, fp64-refine the BAND2 window, final rank
// (value desc, index asc = jax), scatter top-32.
// =====================================================================
__global__ void __launch_bounds__(256) refsel_kernel(
    const float* __restrict__ X, const float* __restrict__ W, float* __restrict__ latent)
{
    __shared__ float sv[NCAND];
    __shared__ int   si[NCAND];
    __shared__ float rv[NCAND];
    __shared__ short ridx[NCAND];
    __shared__ float xs[ND_IN];
    __shared__ int   s_m;
    __shared__ float s_v32;

    const int row = blockIdx.x;
    const int t = threadIdx.x;
    const int wid = t >> 5, lane = t & 31;
    int cnt = g_cand_cnt[row];
    if (cnt > NCAND) cnt = NCAND;

    if (t < NCAND) {
        sv[t] = (t < cnt) ? g_cand_val[row * NCAND + t] : -1e30f;
        si[t] = (t < cnt) ? g_cand_idx[row * NCAND + t] : 0x7fffffff;
        rv[t] = -1e30f;
    }
    for (int k = t; k < ND_IN; k += 256) xs[k] = X[(size_t)row * ND_IN + k];
    if (t == 0) s_m = 0;
    if (t < K_TOP) { g_tk_idx[row * K_TOP + t] = 0; g_tk_val[row * K_TOP + t] = 0.0f; }
    __syncthreads();

    // approx rank -> approx 32nd value
    if (t < cnt) {
        const float v = sv[t];
        const int  ix = si[t];
        int rank = 0;
        #pragma unroll 8
        for (int j = 0; j < NCAND; ++j)
            rank += (sv[j] > v) || (sv[j] == v && si[j] < ix);
        if (rank == K_TOP - 1) s_v32 = v;
    }
    __syncthreads();
    const float band = s_v32 - BAND2;

    if (t < cnt && sv[t] >= band) {
        int p = atomicAdd(&s_m, 1);
        ridx[p] = (short)t;
    }
    __syncthreads();
    const int m = s_m;

    // fp64 dots, one warp per refined candidate
    for (int r = wid; r < m; r += 8) {
        const int c = ridx[r];
        const float* w = W + (size_t)si[c] * ND_IN;
        double s = 0.0;
        #pragma unroll 4
        for (int k = lane; k < ND_IN; k += 32) s = fma((double)xs[k], (double)w[k], s);
        #pragma unroll
        for (int o = 16; o; o >>= 1) s += __shfl_xor_sync(0xffffffffu, s, o);
        if (lane == 0) rv[c] = (float)(s > 0.0 ? s : 0.0);
    }
    __syncthreads();

    // final rank among refined (unrefined stay -1e30) + scatter
    if (t < cnt && rv[t] > -1e29f) {
        const float v = rv[t];
        const int  ix = si[t];
        int rank = 0;
        #pragma unroll 8
        for (int j = 0; j < NCAND; ++j)
            rank += (rv[j] > v) || (rv[j] == v && si[j] < ix);
        if (rank < K_TOP) {
            latent[(size_t)row * ND_HID + ix] = v;
            g_tk_idx[row * K_TOP + rank] = ix;
            g_tk_val[row * K_TOP + rank] = v;
        }
    }
}

// =====================================================================
// transpose W_dec -> g_WdecT
// =====================================================================
__global__ void transpose_kernel(const float* __restrict__ W)
{
    __shared__ float t[32][33];
    const int tx = threadIdx.x, ty = threadIdx.y;
    const int h0 = blockIdx.x * 32;
    const int i0 = blockIdx.y * 32;
    #pragma unroll
    for (int j = ty; j < 32; j += 8)
        t[j][tx] = W[(size_t)(i0 + j) * ND_HID + h0 + tx];
    __syncthreads();
    #pragma unroll
    for (int j = ty; j < 32; j += 8)
        g_WdecT[(size_t)(h0 + j) * ND_IN + i0 + tx] = t[tx][j];
}

// =====================================================================
// sparse decoder
// =====================================================================
__global__ void __launch_bounds__(256) recon_kernel(float* __restrict__ recon)
{
    __shared__ int   si[K_TOP];
    __shared__ float sv[K_TOP];
    const int row = blockIdx.x;
    const int tid = threadIdx.x;
    if (tid < K_TOP) {
        si[tid] = g_tk_idx[row * K_TOP + tid];
        sv[tid] = g_tk_val[row * K_TOP + tid];
    }
    __syncthreads();
    float a0 = 0.f, a1 = 0.f, a2 = 0.f;
    #pragma unroll 4
    for (int j = 0; j < K_TOP; ++j) {
        const float* w = g_WdecT + (size_t)si[j] * ND_IN;
        float v = sv[j];
        a0 += v * w[tid];
        a1 += v * w[tid + 256];
        a2 += v * w[tid + 512];
    }
    float* r = recon + (size_t)row * ND_IN;
    r[tid] = a0; r[tid + 256] = a1; r[tid + 512] = a2;
}

// =====================================================================
extern "C" void kernel_launch(void* const* d_in, const int* in_sizes, int n_in,
                              void* d_out, int out_size)
{
    (void)in_sizes; (void)n_in; (void)out_size;
    const float* x     = (const float*)d_in[0];
    const float* W_enc = (const float*)d_in[1];
    const float* W_dec = (const float*)d_in[2];
    float* latent = (float*)d_out;
    float* recon  = (float*)d_out + (size_t)NB_ROWS * ND_HID;

    // 0) bf16 operand conversion
    conv_x_kernel<<<NB_ROWS * ND_IN / 1024, 256>>>(x);
    conv_w_kernel<<<ND_HID * ND_IN / 1024, 256>>>(W_enc);

    // 1) bf16 warp-MMA GEMM + relu -> dense latent (2 CTAs/SM)
    cudaFuncSetAttribute(wm_gemm_kernel, cudaFuncAttributeMaxDynamicSharedMemorySize, SMEM_REQ);
    wm_gemm_kernel<<<dim3(NB_ROWS / TM, ND_HID / TN), 256, SMEM_REQ>>>(latent);

    // 2) histogram nomination + in-place row zeroing (no smem row buffer)
    cand_kernel<<<NB_ROWS, 256>>>(latent);

    // 3) fp64 refine + select + scatter
    refsel_kernel<<<NB_ROWS, 256>>>(x, W_enc, latent);

    // 4) transpose decoder weights
    transpose_kernel<<<dim3(ND_HID / 32, ND_IN / 32), dim3(32, 8)>>>(W_dec);

    // 5) sparse decoder
    recon_kernel<<<NB_ROWS, 256>>>(recon);
}

// round 15
// speedup vs baseline: 2.6688x; 1.0637x over previous
#include <cuda_runtime.h>
#include <cuda_bf16.h>
#include <cstdint>

#define NB_ROWS 8192
#define ND_IN   768
#define ND_HID  16384
#define K_TOP   32
#define NCAND   128
#define NBIN    512            // bf16-bit bins covering [1.0, 8.0)
#define BAND2   0.04f          // fp64-refine band below approx 32nd value
#define TMARG   0.06f          // nomination margin below bin edge

#define KDIM   ND_IN           // 768
#define TM     128
#define TN     128
#define BK     64              // bf16 per chunk (128 bytes per row)
#define NCHUNK (KDIM / BK)     // 12
#define NSTAGE 3
#define STAGE_BYTES 32768      // A 16KB + B 16KB
#define SMEM_REQ (NSTAGE * STAGE_BYTES)   // 96KB -> 2 CTAs/SM

// ---------------- device scratch (static, allocation-free) ----------------
__device__ __align__(256) __nv_bfloat16 g_Ab[(size_t)NB_ROWS * KDIM];   // 12.6 MB
__device__ __align__(256) __nv_bfloat16 g_Bb[(size_t)ND_HID * KDIM];    // 25 MB
__device__ __align__(256) __nv_bfloat16 g_Lbf[(size_t)NB_ROWS * ND_HID];// 268 MB approx latent
__device__ float g_WdecT[(size_t)ND_HID * ND_IN];                       // 50 MB
__device__ int   g_tk_idx[NB_ROWS * K_TOP];
__device__ float g_tk_val[NB_ROWS * K_TOP];

// ---------------- PTX helpers (baseline compute_103 only!) ----------------
__device__ __forceinline__ uint32_t smem_u32(const void* p) {
    uint32_t a;
    asm("{ .reg .u64 t; cvta.to.shared.u64 t, %1; cvt.u32.u64 %0, t; }" : "=r"(a) : "l"(p));
    return a;
}

__device__ __forceinline__ void cp16(uint32_t dst, const void* src) {
    asm volatile("cp.async.cg.shared.global [%0], [%1], 16;" :: "r"(dst), "l"(src));
}
#define CP_COMMIT() asm volatile("cp.async.commit_group;" ::: "memory")
#define CP_WAIT2()  asm volatile("cp.async.wait_group 2;" ::: "memory")

__device__ __forceinline__ void ldsm4(uint32_t& r0, uint32_t& r1, uint32_t& r2, uint32_t& r3,
                                      uint32_t addr) {
    asm volatile("ldmatrix.sync.aligned.m8n8.x4.shared.b16 {%0,%1,%2,%3}, [%4];"
                 : "=r"(r0), "=r"(r1), "=r"(r2), "=r"(r3) : "r"(addr));
}

__device__ __forceinline__ void mma16816(float* c, uint32_t a0, uint32_t a1, uint32_t a2,
                                         uint32_t a3, uint32_t b0, uint32_t b1) {
    asm volatile(
        "mma.sync.aligned.m16n8k16.row.col.f32.bf16.bf16.f32 "
        "{%0,%1,%2,%3}, {%4,%5,%6,%7}, {%8,%9}, {%0,%1,%2,%3};"
        : "+f"(c[0]), "+f"(c[1]), "+f"(c[2]), "+f"(c[3])
        : "r"(a0), "r"(a1), "r"(a2), "r"(a3), "r"(b0), "r"(b1));
}

// pack (lo=a, hi=b) into bf16x2
__device__ __forceinline__ uint32_t pack_bf16x2(float a, float b) {
    uint32_t r;
    asm("cvt.rn.bf16x2.f32 %0, %1, %2;" : "=r"(r) : "f"(b), "f"(a));
    return r;
}

// =====================================================================
// Prep: fp32 -> bf16 conversion (coalesced)
// =====================================================================
__global__ void conv_x_kernel(const float* __restrict__ X) {
    int i = (blockIdx.x * 256 + threadIdx.x) * 4;
    float4 v = *(const float4*)(X + i);
    uint2 o = make_uint2(pack_bf16x2(v.x, v.y), pack_bf16x2(v.z, v.w));
    *(uint2*)(g_Ab + i) = o;
}
__global__ void conv_w_kernel(const float* __restrict__ W) {
    int i = (blockIdx.x * 256 + threadIdx.x) * 4;
    float4 v = *(const float4*)(W + i);
    uint2 o = make_uint2(pack_bf16x2(v.x, v.y), pack_bf16x2(v.z, v.w));
    *(uint2*)(g_Bb + i) = o;
}
__global__ void zero_latent_kernel(float* __restrict__ L) {
    size_t i = ((size_t)blockIdx.x * 256 + threadIdx.x) * 4;
    *(float4*)(L + i) = make_float4(0.f, 0.f, 0.f, 0.f);
}

// =====================================================================
// Warp-MMA GEMM (bf16): Lbf[m,n] = relu( sum_k A[m,k]*B[n,k] )  (bf16 store)
// CTA 128x128, 8 warps (2Mx4N), warp tile 64x32, 3-stage cp.async,
// 2 CTAs/SM (core measured 589us round 12).
// =====================================================================
__global__ void __launch_bounds__(256, 2) wm_gemm_kernel()
{
    extern __shared__ __align__(128) char smem_raw[];
    const uint32_t smem = smem_u32(smem_raw);

    const int tid  = threadIdx.x;
    const int wid  = tid >> 5;
    const int lane = tid & 31;
    const int wm   = wid & 1;        // 2 warp-rows (M)
    const int wn   = wid >> 1;       // 4 warp-cols (N)
    const int m0 = blockIdx.x * TM;  // M fastest
    const int n0 = blockIdx.y * TN;

    auto load_chunk = [&](int t, int s) {
        const char* Ab = (const char*)g_Ab;
        const char* Bb = (const char*)g_Bb;
        const size_t kb = (size_t)t * (BK * 2);
        const uint32_t aS = smem + s * STAGE_BYTES;
        const uint32_t bS = aS + 16384;
        #pragma unroll
        for (int i = 0; i < 4; ++i) {                 // A: 1024 x 16B
            int gi = tid + (i << 8);
            int r = gi >> 3, g = gi & 7;
            uint32_t col = g * 16;
            uint32_t off = r * 128 + (col ^ ((r & 7) << 4));
            cp16(aS + off, Ab + (size_t)(m0 + r) * (KDIM * 2) + kb + col);
        }
        #pragma unroll
        for (int i = 0; i < 4; ++i) {                 // B: 1024 x 16B
            int gi = tid + (i << 8);
            int r = gi >> 3, g = gi & 7;
            uint32_t col = g * 16;
            uint32_t off = r * 128 + (col ^ ((r & 7) << 4));
            cp16(bS + off, Bb + (size_t)(n0 + r) * (KDIM * 2) + kb + col);
        }
        CP_COMMIT();
    };

    const int lr = lane & 15;
    const uint32_t lc = (lane >> 4) * 16;
    const uint32_t xr = (uint32_t)(lr & 7) << 4;
    uint32_t rbA[4], rbB[2];
    #pragma unroll
    for (int mt = 0; mt < 4; ++mt) rbA[mt] = (uint32_t)(wm * 64 + mt * 16 + lr) * 128;
    #pragma unroll
    for (int p = 0; p < 2; ++p)    rbB[p]  = (uint32_t)(wn * 32 + p * 16 + lr) * 128;

    float acc[4][4][4];
    #pragma unroll
    for (int a = 0; a < 4; ++a)
        #pragma unroll
        for (int b = 0; b < 4; ++b)
            #pragma unroll
            for (int c = 0; c < 4; ++c) acc[a][b][c] = 0.0f;

    load_chunk(0, 0);
    load_chunk(1, 1);

    for (int t = 0; t < NCHUNK; ++t) {
        if (t + 2 < NCHUNK) load_chunk(t + 2, (t + 2) % NSTAGE);
        else                CP_COMMIT();
        CP_WAIT2();
        __syncthreads();

        const uint32_t aS = smem + (t % NSTAGE) * STAGE_BYTES;
        const uint32_t bS = aS + 16384;
        #pragma unroll
        for (int ks = 0; ks < 4; ++ks) {
            const uint32_t colb = (ks * 32 + lc) ^ xr;
            uint32_t af[4][4], bf[2][4];
            #pragma unroll
            for (int mt = 0; mt < 4; ++mt)
                ldsm4(af[mt][0], af[mt][1], af[mt][2], af[mt][3], aS + rbA[mt] + colb);
            #pragma unroll
            for (int p = 0; p < 2; ++p)
                ldsm4(bf[p][0], bf[p][1], bf[p][2], bf[p][3], bS + rbB[p] + colb);
            #pragma unroll
            for (int mt = 0; mt < 4; ++mt)
                #pragma unroll
                for (int j = 0; j < 4; ++j) {
                    const int p = j >> 1, h = j & 1;
                    mma16816(acc[mt][j], af[mt][0], af[mt][1], af[mt][2], af[mt][3],
                             bf[p][h], bf[p][h + 2]);
                }
        }
        __syncthreads();
    }

    // ---- epilogue: relu + bf16x2 store (268 MB total) ----
    const int gid = lane >> 2;
    const int tig = lane & 3;
    #pragma unroll
    for (int mt = 0; mt < 4; ++mt) {
        const int r0 = m0 + wm * 64 + mt * 16 + gid;
        #pragma unroll
        for (int j = 0; j < 4; ++j) {
            const int col = n0 + wn * 32 + j * 8 + tig * 2;
            uint32_t lo = pack_bf16x2(fmaxf(acc[mt][j][0], 0.f), fmaxf(acc[mt][j][1], 0.f));
            uint32_t hi = pack_bf16x2(fmaxf(acc[mt][j][2], 0.f), fmaxf(acc[mt][j][3], 0.f));
            *(uint32_t*)(g_Lbf + (size_t)r0 * ND_HID + col)       = lo;
            *(uint32_t*)(g_Lbf + (size_t)(r0 + 8) * ND_HID + col) = hi;
        }
    }
}

// =====================================================================
// Fused nominate + refine + select. One CTA (256 thr) per row.
// Pass 1: histogram of bf16 bits >= 1.0 (bins = bits-0x3F80, [1,8)).
// Cutoff = edge(b*) - TMARG. Pass 2: collect (idx, val) into smem.
// Approx rank -> v32; fp64-refine the BAND2 window; exact rank; scatter.
// Margins: approx err <= 0.016 (5sigma gemm + bf16 quant); TMARG=0.06,
// BAND2=0.04 both exceed 2x that bound.
// =====================================================================
__global__ void __launch_bounds__(256) candrefsel_kernel(
    const float* __restrict__ X, const float* __restrict__ W, float* __restrict__ latent)
{
    __shared__ int   hist[NBIN];
    __shared__ float sv[NCAND];
    __shared__ int   si[NCAND];
    __shared__ float rv[NCAND];
    __shared__ short ridx[NCAND];
    __shared__ float xs[ND_IN];
    __shared__ int   s_slot, s_m;
    __shared__ float s_Tf, s_v32;

    const int row = blockIdx.x;
    const int t = threadIdx.x;
    const int wid = t >> 5, lane = t & 31;
    const uint4* Lr4 = (const uint4*)(g_Lbf + (size_t)row * ND_HID);   // 2048 uint4

    #pragma unroll
    for (int b = t; b < NBIN; b += 256) hist[b] = 0;
    if (t == 0) { s_slot = 0; s_m = 0; s_v32 = 0.f; }
    for (int k = t; k < ND_IN; k += 256) xs[k] = X[(size_t)row * ND_IN + k];
    if (t < K_TOP) { g_tk_idx[row * K_TOP + t] = 0; g_tk_val[row * K_TOP + t] = 0.0f; }
    __syncthreads();

    // ---- pass 1: histogram (8 bf16 per uint4) ----
    #pragma unroll
    for (int i = 0; i < ND_HID / 8 / 256; ++i) {
        uint4 v = Lr4[t + (i << 8)];
        uint32_t w[4] = { v.x, v.y, v.z, v.w };
        #pragma unroll
        for (int j = 0; j < 4; ++j) {
            uint32_t h0 = w[j] & 0xFFFFu, h1 = w[j] >> 16;
            if (h0 >= 0x3F80u) { uint32_t b = h0 - 0x3F80u; atomicAdd(&hist[b < NBIN ? b : NBIN - 1], 1); }
            if (h1 >= 0x3F80u) { uint32_t b = h1 - 0x3F80u; atomicAdd(&hist[b < NBIN ? b : NBIN - 1], 1); }
        }
    }
    __syncthreads();

    if (t == 0) {
        int cum = 0, bstar = -1;
        for (int b = NBIN - 1; b >= 0; --b) {
            cum += hist[b];
            if (cum >= K_TOP) { bstar = b; break; }
        }
        float edge = (bstar >= 0)
                   ? __uint_as_float((0x3F80u + (unsigned)bstar) << 16)
                   : 1.0f;      // statistically unreachable
        s_Tf = edge - TMARG;
    }
    __syncthreads();
    const float Tf = s_Tf;

    // ---- pass 2: collect candidates (row is L2-hot) ----
    #pragma unroll
    for (int i = 0; i < ND_HID / 8 / 256; ++i) {
        uint4 v = Lr4[t + (i << 8)];
        const int base = (t + (i << 8)) * 8;
        uint32_t w[4] = { v.x, v.y, v.z, v.w };
        #pragma unroll
        for (int j = 0; j < 4; ++j) {
            float f0 = __uint_as_float((w[j] & 0xFFFFu) << 16);
            float f1 = __uint_as_float((w[j] >> 16) << 16);
            if (f0 >= Tf) { int s = atomicAdd(&s_slot, 1); if (s < NCAND) { si[s] = base + j * 2;     sv[s] = f0; } }
            if (f1 >= Tf) { int s = atomicAdd(&s_slot, 1); if (s < NCAND) { si[s] = base + j * 2 + 1; sv[s] = f1; } }
        }
    }
    __syncthreads();
    int cnt = s_slot < NCAND ? s_slot : NCAND;
    if (t >= cnt && t < NCAND) { sv[t] = -1e30f; si[t] = 0x7fffffff; }
    if (t < NCAND) rv[t] = -1e30f;
    __syncthreads();

    // ---- approx rank -> approx 32nd value ----
    if (t < cnt) {
        const float v = sv[t];
        const int  ix = si[t];
        int rank = 0;
        #pragma unroll 8
        for (int j = 0; j < NCAND; ++j)
            rank += (sv[j] > v) || (sv[j] == v && si[j] < ix);
        if (rank == K_TOP - 1) s_v32 = v;
    }
    __syncthreads();
    const float band = s_v32 - BAND2;

    if (t < cnt && sv[t] >= band) {
        int p = atomicAdd(&s_m, 1);
        ridx[p] = (short)t;
    }
    __syncthreads();
    const int m = s_m;

    // ---- fp64 dots, one warp per refined candidate ----
    for (int r = wid; r < m; r += 8) {
        const int c = ridx[r];
        const float* w = W + (size_t)si[c] * ND_IN;
        double s = 0.0;
        #pragma unroll 4
        for (int k = lane; k < ND_IN; k += 32) s = fma((double)xs[k], (double)w[k], s);
        #pragma unroll
        for (int o = 16; o; o >>= 1) s += __shfl_xor_sync(0xffffffffu, s, o);
        if (lane == 0) rv[c] = (float)(s > 0.0 ? s : 0.0);
    }
    __syncthreads();

    // ---- final exact rank (value desc, index asc = jax) + scatter ----
    if (t < cnt && rv[t] > -1e29f) {
        const float v = rv[t];
        const int  ix = si[t];
        int rank = 0;
        #pragma unroll 8
        for (int j = 0; j < NCAND; ++j)
            rank += (rv[j] > v) || (rv[j] == v && si[j] < ix);
        if (rank < K_TOP) {
            latent[(size_t)row * ND_HID + ix] = v;
            g_tk_idx[row * K_TOP + rank] = ix;
            g_tk_val[row * K_TOP + rank] = v;
        }
    }
}

// =====================================================================
// transpose W_dec -> g_WdecT
// =====================================================================
__global__ void transpose_kernel(const float* __restrict__ W)
{
    __shared__ float t[32][33];
    const int tx = threadIdx.x, ty = threadIdx.y;
    const int h0 = blockIdx.x * 32;
    const int i0 = blockIdx.y * 32;
    #pragma unroll
    for (int j = ty; j < 32; j += 8)
        t[j][tx] = W[(size_t)(i0 + j) * ND_HID + h0 + tx];
    __syncthreads();
    #pragma unroll
    for (int j = ty; j < 32; j += 8)
        g_WdecT[(size_t)(h0 + j) * ND_IN + i0 + tx] = t[tx][j];
}

// =====================================================================
// sparse decoder
// =====================================================================
__global__ void __launch_bounds__(256) recon_kernel(float* __restrict__ recon)
{
    __shared__ int   si[K_TOP];
    __shared__ float sv[K_TOP];
    const int row = blockIdx.x;
    const int tid = threadIdx.x;
    if (tid < K_TOP) {
        si[tid] = g_tk_idx[row * K_TOP + tid];
        sv[tid] = g_tk_val[row * K_TOP + tid];
    }
    __syncthreads();
    float a0 = 0.f, a1 = 0.f, a2 = 0.f;
    #pragma unroll 4
    for (int j = 0; j < K_TOP; ++j) {
        const float* w = g_WdecT + (size_t)si[j] * ND_IN;
        float v = sv[j];
        a0 += v * w[tid];
        a1 += v * w[tid + 256];
        a2 += v * w[tid + 512];
    }
    float* r = recon + (size_t)row * ND_IN;
    r[tid] = a0; r[tid + 256] = a1; r[tid + 512] = a2;
}

// =====================================================================
extern "C" void kernel_launch(void* const* d_in, const int* in_sizes, int n_in,
                              void* d_out, int out_size)
{
    (void)in_sizes; (void)n_in; (void)out_size;
    const float* x     = (const float*)d_in[0];
    const float* W_enc = (const float*)d_in[1];
    const float* W_dec = (const float*)d_in[2];
    float* latent = (float*)d_out;
    float* recon  = (float*)d_out + (size_t)NB_ROWS * ND_HID;

    // 0) bf16 operand conversion
    conv_x_kernel<<<NB_ROWS * ND_IN / 1024, 256>>>(x);
    conv_w_kernel<<<ND_HID * ND_IN / 1024, 256>>>(W_enc);

    // 1) bf16 warp-MMA GEMM + relu -> bf16 approx latent (scratch)
    cudaFuncSetAttribute(wm_gemm_kernel, cudaFuncAttributeMaxDynamicSharedMemorySize, SMEM_REQ);
    wm_gemm_kernel<<<dim3(NB_ROWS / TM, ND_HID / TN), 256, SMEM_REQ>>>();

    // 2) zero the latent output region
    zero_latent_kernel<<<NB_ROWS * ND_HID / 1024, 256>>>(latent);

    // 3) fused nominate + fp64 refine + select + scatter
    candrefsel_kernel<<<NB_ROWS, 256>>>(x, W_enc, latent);

    // 4) transpose decoder weights
    transpose_kernel<<<dim3(ND_HID / 32, ND_IN / 32), dim3(32, 8)>>>(W_dec);

    // 5) sparse decoder
    recon_kernel<<<NB_ROWS, 256>>>(recon);
}